// round 2
// baseline (speedup 1.0000x reference)
#include <cuda_runtime.h>
#include <cuda_fp16.h>
#include <cstdint>

// Problem shape (fixed by the dataset)
#define M_TOT   64          // B*S = 4*16 rows of x
#define K_TOT   4096
#define O_TOT   11008
#define GROUP   128         // int4 quant group size along K
#define NGRP    (K_TOT / GROUP)        // 32
#define GPACK   ((NGRP + 7) / 8)       // 4 packed-zero words per output row

// Tiling
#define BN      64          // outputs per block
#define BK      64          // K chunk per iteration (one quant group covers 2 chunks)
#define PAD     8           // smem padding (halfs) -> conflict-free fragment loads
#define NTHREADS 256

__global__ __launch_bounds__(NTHREADS)
void w4a16_mma_kernel(const float* __restrict__ x,      // fp16 upcast to fp32 by harness
                      const int*   __restrict__ qw,
                      const int*   __restrict__ qz,
                      const float* __restrict__ sc,     // fp16 upcast to fp32 by harness
                      float*       __restrict__ out)
{
    __shared__ __half xs[M_TOT][BK + PAD];   // x tile: all 64 rows x BK
    __shared__ __half ws[BN][BK + PAD];      // dequantized weight tile

    const int tid  = threadIdx.x;
    const int warp = tid >> 5;
    const int lane = tid & 31;
    const int nBase = blockIdx.x * BN;

    // Warp tiling: 2 warps along M (32 rows each), 4 warps along N (16 cols each)
    const int wm = (warp & 1) * 32;
    const int wn = (warp >> 1) * 16;

    const int grp = lane >> 2;   // 0..7  (fragment row group)
    const int tq  = lane & 3;    // 0..3  (fragment quad)

    float acc[2][2][4];
    #pragma unroll
    for (int i = 0; i < 2; i++)
        #pragma unroll
        for (int j = 0; j < 2; j++)
            #pragma unroll
            for (int r = 0; r < 4; r++) acc[i][j][r] = 0.0f;

    for (int kb = 0; kb < K_TOT; kb += BK) {
        // ---- load x tile (fp32 -> fp16): 64 rows x 64 floats = 1024 float4 ----
        #pragma unroll
        for (int r = 0; r < 4; r++) {
            int idx = tid + r * NTHREADS;       // 0..1023
            int m   = idx >> 4;                 // 16 float4 per row
            int c   = idx & 15;                 // float4 index within row
            float4 v = *(const float4*)(x + m * K_TOT + kb + c * 4);
            __half2 h0 = __floats2half2_rn(v.x, v.y);
            __half2 h1 = __floats2half2_rn(v.z, v.w);
            *(__half2*)(&xs[m][c * 4])     = h0;
            *(__half2*)(&xs[m][c * 4 + 2]) = h1;
        }

        // ---- dequantize weight tile: 64 rows x 8 int32 words; 2 per thread ----
        {
            const int g = kb / GROUP;           // constant for whole chunk
            #pragma unroll
            for (int r = 0; r < 2; r++) {
                int idx = tid + r * NTHREADS;   // 0..511
                int n   = idx >> 3;
                int cw  = idx & 7;              // int32 word within chunk
                int o   = nBase + n;
                unsigned w32 = (unsigned)qw[o * (K_TOT / 8) + (kb >> 3) + cw];
                unsigned zw  = (unsigned)qz[o * GPACK + (g >> 3)];
                int z = (int)((zw >> ((g & 7) * 4)) & 15u);
                __half  s  = __float2half_rn(sc[o * NGRP + g]);
                __half2 s2 = __half2half2(s);
                __half2 vals[4];
                #pragma unroll
                for (int j = 0; j < 4; j++) {
                    int q0 = (int)((w32 >> (8 * j))     & 15u);
                    int q1 = (int)((w32 >> (8 * j + 4)) & 15u);
                    vals[j] = __hmul2(__halves2half2(__int2half_rn(q0 - z),
                                                     __int2half_rn(q1 - z)), s2);
                }
                *(uint4*)(&ws[n][cw * 8]) = *(uint4*)vals;
            }
        }
        __syncthreads();

        // ---- MMA over the chunk, k16 steps ----
        #pragma unroll
        for (int kk = 0; kk < BK; kk += 16) {
            // A fragments (x, row-major 16x16): two M tiles
            unsigned a[2][4];
            #pragma unroll
            for (int mt = 0; mt < 2; mt++) {
                int row0 = wm + mt * 16 + grp;
                int c0   = kk + tq * 2;
                a[mt][0] = *(const unsigned*)(&xs[row0    ][c0    ]);
                a[mt][1] = *(const unsigned*)(&xs[row0 + 8][c0    ]);
                a[mt][2] = *(const unsigned*)(&xs[row0    ][c0 + 8]);
                a[mt][3] = *(const unsigned*)(&xs[row0 + 8][c0 + 8]);
            }
            // B fragments (w, col-major 16x8 == w[n][k] k-contiguous): two N tiles
            unsigned b[2][2];
            #pragma unroll
            for (int nt = 0; nt < 2; nt++) {
                int col = wn + nt * 8 + grp;
                int k0  = kk + tq * 2;
                b[nt][0] = *(const unsigned*)(&ws[col][k0    ]);
                b[nt][1] = *(const unsigned*)(&ws[col][k0 + 8]);
            }
            #pragma unroll
            for (int mt = 0; mt < 2; mt++)
                #pragma unroll
                for (int nt = 0; nt < 2; nt++)
                    asm volatile(
                        "mma.sync.aligned.m16n8k16.row.col.f32.f16.f16.f32 "
                        "{%0,%1,%2,%3}, {%4,%5,%6,%7}, {%8,%9}, {%0,%1,%2,%3};\n"
                        : "+f"(acc[mt][nt][0]), "+f"(acc[mt][nt][1]),
                          "+f"(acc[mt][nt][2]), "+f"(acc[mt][nt][3])
                        : "r"(a[mt][0]), "r"(a[mt][1]), "r"(a[mt][2]), "r"(a[mt][3]),
                          "r"(b[nt][0]), "r"(b[nt][1]));
        }
        __syncthreads();
    }

    // ---- epilogue: C fragment layout -> out[m][o] fp32 ----
    #pragma unroll
    for (int mt = 0; mt < 2; mt++) {
        #pragma unroll
        for (int nt = 0; nt < 2; nt++) {
            int row = wm + mt * 16 + grp;
            int col = nBase + wn + nt * 8 + tq * 2;
            out[row * O_TOT + col]           = acc[mt][nt][0];
            out[row * O_TOT + col + 1]       = acc[mt][nt][1];
            out[(row + 8) * O_TOT + col]     = acc[mt][nt][2];
            out[(row + 8) * O_TOT + col + 1] = acc[mt][nt][3];
        }
    }
}

extern "C" void kernel_launch(void* const* d_in, const int* in_sizes, int n_in,
                              void* d_out, int out_size)
{
    const float* x  = (const float*)d_in[0];   // [64, 4096] (fp16 upcast to fp32)
    const int*   qw = (const int*)  d_in[1];   // [11008, 512] int32
    const int*   qz = (const int*)  d_in[2];   // [11008, 4]   int32
    const float* sc = (const float*)d_in[3];   // [11008, 32]  (fp16 upcast to fp32)
    float*       out = (float*)d_out;          // [64, 11008]  fp32

    dim3 grid(O_TOT / BN);      // 172 blocks
    dim3 block(NTHREADS);
    w4a16_mma_kernel<<<grid, block>>>(x, qw, qz, sc, out);
}

// round 3
// speedup vs baseline: 1.0584x; 1.0584x over previous
#include <cuda_runtime.h>
#include <cuda_fp16.h>
#include <cstdint>

// Problem shape (fixed by the dataset)
#define M_TOT   64          // B*S = 4*16 rows of x
#define K_TOT   4096
#define O_TOT   11008
#define GROUP   128         // int4 quant group size along K
#define NGRP    (K_TOT / GROUP)        // 32
#define GPACK   ((NGRP + 7) / 8)       // 4 packed-zero words per row

// Tiling
#define BN      64          // outputs per block
#define BK      128         // K chunk = exactly one quant group
#define NCH     (K_TOT / BK)           // 32 chunks
#define PAD     8           // smem padding (halfs) -> conflict-free fragment loads
#define NTHREADS 256

__global__ __launch_bounds__(NTHREADS)
void w4a16_mma_kernel(const float* __restrict__ x,      // fp16 upcast to fp32 by harness
                      const int*   __restrict__ qw,
                      const int*   __restrict__ qz,
                      const float* __restrict__ sc,     // fp16 upcast to fp32 by harness
                      float*       __restrict__ out)
{
    __shared__ __half xs[M_TOT][BK + PAD];   // 64 x 136 halfs
    __shared__ __half ws[BN][BK + PAD];      // 64 x 136 halfs

    const int tid  = threadIdx.x;
    const int warp = tid >> 5;
    const int lane = tid & 31;
    const int nBase = blockIdx.x * BN;

    // Warp tiling: 2 warps along M (32 rows), 4 warps along N (16 cols)
    const int wm = (warp & 1) * 32;
    const int wn = (warp >> 1) * 16;

    const int grp = lane >> 2;   // 0..7
    const int tq  = lane & 3;    // 0..3

    // Per-thread staging assignments (constant across chunks)
    const int wrow = tid >> 2;               // weight row 0..63 (one row per thread)
    const int wseg = tid & 3;                // 4 uint4 words per row-chunk, seg*4..seg*4+3
    const int wo   = nBase + wrow;

    float acc[2][2][4];
    #pragma unroll
    for (int i = 0; i < 2; i++)
        #pragma unroll
        for (int j = 0; j < 2; j++)
            #pragma unroll
            for (int r = 0; r < 4; r++) acc[i][j][r] = 0.0f;

    // ---- staging registers (double-buffer through RF) ----
    float4  xr[8];      // 8 float4 = 32 floats of x per thread per chunk
    uint4   qr;         // 4 packed int32 words (32 int4 values) of one weight row
    __half2 s2r;        // group scale (broadcast pair)
    int     zr;         // group zero point

    // load stage: issue all global loads for chunk at kb
    auto load_stage = [&](int kb) {
        #pragma unroll
        for (int r = 0; r < 8; r++) {
            int idx = tid + r * NTHREADS;    // 0..2047
            int m   = idx >> 5;              // 32 float4 per row of 128 floats
            int c   = idx & 31;
            xr[r] = *(const float4*)(x + m * K_TOT + kb + c * 4);
        }
        qr = *(const uint4*)(qw + wo * (K_TOT / 8) + (kb >> 3) + wseg * 4);
        const int g = kb / GROUP;
        unsigned zw = (unsigned)qz[wo * GPACK + (g >> 3)];
        zr  = (int)((zw >> ((g & 7) * 4)) & 15u);
        s2r = __half2half2(__float2half_rn(sc[wo * NGRP + g]));
    };

    // store stage: regs -> smem (dequantize weights, downconvert x)
    auto store_stage = [&]() {
        #pragma unroll
        for (int r = 0; r < 8; r++) {
            int idx = tid + r * NTHREADS;
            int m   = idx >> 5;
            int c   = idx & 31;
            *(__half2*)(&xs[m][c * 4])     = __floats2half2_rn(xr[r].x, xr[r].y);
            *(__half2*)(&xs[m][c * 4 + 2]) = __floats2half2_rn(xr[r].z, xr[r].w);
        }
        const unsigned wv[4] = {qr.x, qr.y, qr.z, qr.w};
        #pragma unroll
        for (int j = 0; j < 4; j++) {
            unsigned w32 = wv[j];
            __half2 vals[4];
            #pragma unroll
            for (int p = 0; p < 4; p++) {
                int q0 = (int)((w32 >> (8 * p))     & 15u);
                int q1 = (int)((w32 >> (8 * p + 4)) & 15u);
                vals[p] = __hmul2(__halves2half2(__int2half_rn(q0 - zr),
                                                 __int2half_rn(q1 - zr)), s2r);
            }
            *(uint4*)(&ws[wrow][(wseg * 4 + j) * 8]) = *(uint4*)vals;
        }
    };

    load_stage(0);
    store_stage();

    for (int i = 0; i < NCH; i++) {
        __syncthreads();                 // tile i ready in smem

        if (i + 1 < NCH) load_stage((i + 1) * BK);   // LDGs in flight during MMA

        // ---- MMA over chunk i ----
        #pragma unroll
        for (int kk = 0; kk < BK; kk += 16) {
            unsigned a[2][4];
            #pragma unroll
            for (int mt = 0; mt < 2; mt++) {
                int row0 = wm + mt * 16 + grp;
                int c0   = kk + tq * 2;
                a[mt][0] = *(const unsigned*)(&xs[row0    ][c0    ]);
                a[mt][1] = *(const unsigned*)(&xs[row0 + 8][c0    ]);
                a[mt][2] = *(const unsigned*)(&xs[row0    ][c0 + 8]);
                a[mt][3] = *(const unsigned*)(&xs[row0 + 8][c0 + 8]);
            }
            unsigned b[2][2];
            #pragma unroll
            for (int nt = 0; nt < 2; nt++) {
                int col = wn + nt * 8 + grp;
                int k0  = kk + tq * 2;
                b[nt][0] = *(const unsigned*)(&ws[col][k0    ]);
                b[nt][1] = *(const unsigned*)(&ws[col][k0 + 8]);
            }
            #pragma unroll
            for (int mt = 0; mt < 2; mt++)
                #pragma unroll
                for (int nt = 0; nt < 2; nt++)
                    asm volatile(
                        "mma.sync.aligned.m16n8k16.row.col.f32.f16.f16.f32 "
                        "{%0,%1,%2,%3}, {%4,%5,%6,%7}, {%8,%9}, {%0,%1,%2,%3};\n"
                        : "+f"(acc[mt][nt][0]), "+f"(acc[mt][nt][1]),
                          "+f"(acc[mt][nt][2]), "+f"(acc[mt][nt][3])
                        : "r"(a[mt][0]), "r"(a[mt][1]), "r"(a[mt][2]), "r"(a[mt][3]),
                          "r"(b[nt][0]), "r"(b[nt][1]));
        }

        __syncthreads();                 // all warps done reading tile i

        if (i + 1 < NCH) store_stage();  // stalls here (not earlier) on LDG arrival
    }

    // ---- epilogue: C fragment layout -> out[m][o] fp32 ----
    #pragma unroll
    for (int mt = 0; mt < 2; mt++) {
        #pragma unroll
        for (int nt = 0; nt < 2; nt++) {
            int row = wm + mt * 16 + grp;
            int col = nBase + wn + nt * 8 + tq * 2;
            out[row * O_TOT + col]           = acc[mt][nt][0];
            out[row * O_TOT + col + 1]       = acc[mt][nt][1];
            out[(row + 8) * O_TOT + col]     = acc[mt][nt][2];
            out[(row + 8) * O_TOT + col + 1] = acc[mt][nt][3];
        }
    }
}

extern "C" void kernel_launch(void* const* d_in, const int* in_sizes, int n_in,
                              void* d_out, int out_size)
{
    const float* x  = (const float*)d_in[0];   // [64, 4096] (fp16 upcast to fp32)
    const int*   qw = (const int*)  d_in[1];   // [11008, 512] int32
    const int*   qz = (const int*)  d_in[2];   // [11008, 4]   int32
    const float* sc = (const float*)d_in[3];   // [11008, 32]  (fp16 upcast to fp32)
    float*       out = (float*)d_out;          // [64, 11008]  fp32

    dim3 grid(O_TOT / BN);      // 172 blocks
    dim3 block(NTHREADS);
    w4a16_mma_kernel<<<grid, block>>>(x, qw, qz, sc, out);
}